// round 3
// baseline (speedup 1.0000x reference)
#include <cuda_runtime.h>

#define MAXN 50000
#define D 128
#define BM 128
#define BK 32
#define BMP 132   // padded As stride (16B-aligned: 132*4=528)

// Scratch (no cudaMalloc allowed)
__device__ float g_buf0[MAXN * D];   // aggregated input, later h2 raw
__device__ float g_buf1[MAXN * D];   // h1 raw
__device__ float g_sum[2][D];
__device__ float g_sq[2][D];
__device__ float g_scale[2][D];
__device__ float g_shift[2][D];
__device__ int   g_is64;

// ---------------------------------------------------------------------------
// Detect int64 vs int32 edge_index (JAX x64 ambiguity).
__global__ void detect_kernel(const long long* __restrict__ ei, int E, int N) {
    __shared__ int bad;
    if (threadIdx.x == 0) bad = 0;
    __syncthreads();
    int M = min(E, 4096);
    for (int i = threadIdx.x; i < M; i += blockDim.x) {
        long long v = ei[i];
        if (v < 0 || v >= (long long)N) bad = 1;
    }
    __syncthreads();
    if (threadIdx.x == 0) g_is64 = bad ? 0 : 1;
}

// ---------------------------------------------------------------------------
// g_buf0 = (1+eps)*x ; zero stats accumulators
__global__ void init_kernel(const float* __restrict__ x,
                            const float* __restrict__ eps, int total4) {
    int i = blockIdx.x * blockDim.x + threadIdx.x;
    float s = 1.0f + eps[0];
    if (i < total4) {
        float4 v = ((const float4*)x)[i];
        v.x *= s; v.y *= s; v.z *= s; v.w *= s;
        ((float4*)g_buf0)[i] = v;
    }
    if (blockIdx.x == 0 && threadIdx.x < 2 * D) {
        int p = threadIdx.x / D, c = threadIdx.x % D;
        g_sum[p][c] = 0.f;
        g_sq[p][c]  = 0.f;
    }
}

// ---------------------------------------------------------------------------
// One warp per edge: gather x[src] row, vector-reduce into g_buf0[dst].
__global__ void scatter_kernel(const float* __restrict__ x,
                               const void* __restrict__ ei_raw, int E) {
    int e = (blockIdx.x * blockDim.x + threadIdx.x) >> 5;
    if (e >= E) return;
    int lane = threadIdx.x & 31;
    long long s, d;
    if (g_is64) {
        const long long* p = (const long long*)ei_raw;
        s = p[e];
        d = p[E + e];
    } else {
        const int* p = (const int*)ei_raw;
        s = p[e];
        d = p[E + e];
    }
    float4 v = __ldg((const float4*)(x + s * D) + lane);
    float* addr = g_buf0 + d * D + (lane << 2);
    asm volatile("red.global.add.v4.f32 [%0], {%1,%2,%3,%4};"
                 :: "l"(addr), "f"(v.x), "f"(v.y), "f"(v.z), "f"(v.w)
                 : "memory");
}

// ---------------------------------------------------------------------------
// out[N,128] = op(A)[N,128] @ W[128,128] + bias, fused with:
//   - optional input normalization (normPhase >= 0): a = relu(a*scale+shift)
//   - BN stats accumulation (column sum / sumsq of output) into g_sum/g_sq[phase]
// Tile: 128x128, BK=32, 256 threads, 8x8 per thread, plain float accumulators.
__global__ void __launch_bounds__(256, 2)
gemm_kernel(const float* __restrict__ A, const float* __restrict__ W,
            const float* __restrict__ bias, float* __restrict__ out,
            int N, int phase, int normPhase) {
    __shared__ __align__(16) float As[BK][BMP];
    __shared__ __align__(16) float Bs[BK][D];

    int tid = threadIdx.x;
    int tx = tid & 15;        // col group: cols tx*8 .. tx*8+7
    int ty = tid >> 4;        // row group: rows ty*8 .. ty*8+7
    int rowStart = blockIdx.x * BM;

    float acc[8][8];
#pragma unroll
    for (int i = 0; i < 8; i++)
#pragma unroll
        for (int j = 0; j < 8; j++) acc[i][j] = 0.f;

    for (int kc = 0; kc < D; kc += BK) {
        // Load A tile (128x32 = 1024 float4, 4 per thread), transpose into As
#pragma unroll
        for (int l = 0; l < 4; l++) {
            int t   = tid + 256 * l;
            int row = t >> 3;        // 0..127
            int c4  = t & 7;         // k offset c4*4
            int gr  = rowStart + row;
            float4 v = make_float4(0.f, 0.f, 0.f, 0.f);
            if (gr < N) v = ((const float4*)(A + (size_t)gr * D + kc))[c4];
            if (normPhase >= 0) {
                float4 sc = ((const float4*)g_scale[normPhase])[(kc >> 2) + c4];
                float4 sh = ((const float4*)g_shift[normPhase])[(kc >> 2) + c4];
                v.x = fmaxf(v.x * sc.x + sh.x, 0.f);
                v.y = fmaxf(v.y * sc.y + sh.y, 0.f);
                v.z = fmaxf(v.z * sc.z + sh.z, 0.f);
                v.w = fmaxf(v.w * sc.w + sh.w, 0.f);
            }
            As[c4 * 4 + 0][row] = v.x;
            As[c4 * 4 + 1][row] = v.y;
            As[c4 * 4 + 2][row] = v.z;
            As[c4 * 4 + 3][row] = v.w;
        }
        // Load B tile (32x128 = 1024 float4, 4 per thread)
#pragma unroll
        for (int l = 0; l < 4; l++) {
            int t   = tid + 256 * l;
            int row = t >> 5;
            int c4  = t & 31;
            *((float4*)&Bs[row][c4 * 4]) =
                ((const float4*)(W + (size_t)(kc + row) * D))[c4];
        }
        __syncthreads();

#pragma unroll
        for (int kk = 0; kk < BK; kk++) {
            float4 a0 = *((const float4*)&As[kk][ty * 8]);
            float4 a1 = *((const float4*)&As[kk][ty * 8 + 4]);
            float4 b0 = *((const float4*)&Bs[kk][tx * 8]);
            float4 b1 = *((const float4*)&Bs[kk][tx * 8 + 4]);
            float a[8] = {a0.x, a0.y, a0.z, a0.w, a1.x, a1.y, a1.z, a1.w};
            float b[8] = {b0.x, b0.y, b0.z, b0.w, b1.x, b1.y, b1.z, b1.w};
#pragma unroll
            for (int i = 0; i < 8; i++)
#pragma unroll
                for (int j = 0; j < 8; j++)
                    acc[i][j] = fmaf(a[i], b[j], acc[i][j]);
        }
        __syncthreads();
    }

    // Epilogue: bias, store, column stats from registers
    float4 bb0 = ((const float4*)bias)[tx * 2];
    float4 bb1 = ((const float4*)bias)[tx * 2 + 1];
    float bcol[8] = {bb0.x, bb0.y, bb0.z, bb0.w, bb1.x, bb1.y, bb1.z, bb1.w};
    float s[8], q[8];
#pragma unroll
    for (int j = 0; j < 8; j++) { s[j] = 0.f; q[j] = 0.f; }

#pragma unroll
    for (int i = 0; i < 8; i++) {
        int gr = rowStart + ty * 8 + i;
        if (gr < N) {
            float h[8];
#pragma unroll
            for (int j = 0; j < 8; j++) {
                h[j] = acc[i][j] + bcol[j];
                s[j] += h[j];
                q[j] += h[j] * h[j];
            }
            float* o = out + (size_t)gr * D + tx * 8;
            *((float4*)o)       = make_float4(h[0], h[1], h[2], h[3]);
            *((float4*)(o + 4)) = make_float4(h[4], h[5], h[6], h[7]);
        }
    }
    // halve atomic count: combine ty-even/odd lanes (lane xor 16)
#pragma unroll
    for (int j = 0; j < 8; j++) {
        s[j] += __shfl_xor_sync(0xffffffffu, s[j], 16);
        q[j] += __shfl_xor_sync(0xffffffffu, q[j], 16);
    }
    if ((ty & 1) == 0) {
#pragma unroll
        for (int j = 0; j < 8; j++) {
            atomicAdd(&g_sum[phase][tx * 8 + j], s[j]);
            atomicAdd(&g_sq[phase][tx * 8 + j],  q[j]);
        }
    }
}

// ---------------------------------------------------------------------------
__global__ void finalize_kernel(int phase, const float* __restrict__ g,
                                const float* __restrict__ beta, float invN) {
    int c = threadIdx.x;
    float mu  = g_sum[phase][c] * invN;
    float var = g_sq[phase][c] * invN - mu * mu;
    float inv = rsqrtf(var + 1e-5f);
    float sc  = g[c] * inv;
    g_scale[phase][c] = sc;
    g_shift[phase][c] = beta[c] - mu * sc;
}

// ---------------------------------------------------------------------------
// out = relu(h*scale + shift)  (final layer -> d_out)
__global__ void norm_kernel(const float* __restrict__ h, int phase,
                            float* __restrict__ extout, int total4) {
    int i = blockIdx.x * blockDim.x + threadIdx.x;
    if (i >= total4) return;
    int c4 = i & 31;
    float4 v  = ((const float4*)h)[i];
    float4 sc = ((const float4*)g_scale[phase])[c4];
    float4 sh = ((const float4*)g_shift[phase])[c4];
    float4 o;
    o.x = fmaxf(v.x * sc.x + sh.x, 0.f);
    o.y = fmaxf(v.y * sc.y + sh.y, 0.f);
    o.z = fmaxf(v.z * sc.z + sh.z, 0.f);
    o.w = fmaxf(v.w * sc.w + sh.w, 0.f);
    ((float4*)extout)[i] = o;
}

// ---------------------------------------------------------------------------
extern "C" void kernel_launch(void* const* d_in, const int* in_sizes, int n_in,
                              void* d_out, int out_size) {
    const float* x   = (const float*)d_in[0];
    const void*  ei  = d_in[1];
    const float* eps = (const float*)d_in[2];
    const float* W1  = (const float*)d_in[3];
    const float* b1  = (const float*)d_in[4];
    const float* g1  = (const float*)d_in[5];
    const float* be1 = (const float*)d_in[6];
    const float* W2  = (const float*)d_in[7];
    const float* b2  = (const float*)d_in[8];
    const float* g2  = (const float*)d_in[9];
    const float* be2 = (const float*)d_in[10];

    int N = in_sizes[0] / D;
    int E = in_sizes[1] / 2;
    int total4 = N * (D / 4);
    const int TB = 256;

    float* buf0;
    float* buf1;
    cudaGetSymbolAddress((void**)&buf0, g_buf0);
    cudaGetSymbolAddress((void**)&buf1, g_buf1);

    detect_kernel<<<1, 256>>>((const long long*)ei, E, N);
    init_kernel<<<(total4 + TB - 1) / TB, TB>>>(x, eps, total4);

    long long sthreads = (long long)E * 32;
    scatter_kernel<<<(unsigned)((sthreads + TB - 1) / TB), TB>>>(x, ei, E);

    int gblocks = (N + BM - 1) / BM;
    float invN = 1.0f / (float)N;

    // layer 1: h1 = g_buf0 @ W1 + b1  (stats fused)
    gemm_kernel<<<gblocks, 256>>>(buf0, W1, b1, buf1, N, 0, -1);
    finalize_kernel<<<1, D>>>(0, g1, be1, invN);
    // layer 2: h2 = relu(bn(h1)) @ W2 + b2  (norm of h1 fused into A-load)
    gemm_kernel<<<gblocks, 256>>>(buf1, W2, b2, buf0, N, 1, 0);
    finalize_kernel<<<1, D>>>(1, g2, be2, invN);
    // final: d_out = relu(bn(h2))
    norm_kernel<<<(total4 + TB - 1) / TB, TB>>>(buf0, 1, (float*)d_out, total4);
}

// round 4
// speedup vs baseline: 1.0511x; 1.0511x over previous
#include <cuda_runtime.h>

#define MAXN 50000
#define D 128
#define BM 128

typedef unsigned long long ull;

// Scratch (no cudaMalloc allowed)
__device__ float g_buf0[MAXN * D];   // aggregated input, later h2 raw
__device__ float g_buf1[MAXN * D];   // h1 raw
__device__ float g_sum[2][D];
__device__ float g_sq[2][D];
__device__ float g_scale[2][D];
__device__ float g_shift[2][D];
__device__ int   g_is64;

// Dynamic smem: As[128][128] (k-major, transposed A tile) then Bs[128][128]
#define SMEM_BYTES (2 * D * D * 4)

// ---------------------------------------------------------------------------
__device__ __forceinline__ ull pack2(float x, float y) {
    ull d;
    asm("mov.b64 %0, {%1, %2};" : "=l"(d) : "f"(x), "f"(y));
    return d;
}
__device__ __forceinline__ void unpack2(ull d, float& x, float& y) {
    asm("mov.b64 {%0, %1}, %2;" : "=f"(x), "=f"(y) : "l"(d));
}
__device__ __forceinline__ void fma2(ull& d, ull a, ull b) {
    asm("fma.rn.f32x2 %0, %1, %2, %0;" : "+l"(d) : "l"(a), "l"(b));
}

// ---------------------------------------------------------------------------
// Detect int64 vs int32 edge_index (JAX x64 ambiguity).
__global__ void detect_kernel(const long long* __restrict__ ei, int E, int N) {
    __shared__ int bad;
    if (threadIdx.x == 0) bad = 0;
    __syncthreads();
    int M = min(E, 4096);
    for (int i = threadIdx.x; i < M; i += blockDim.x) {
        long long v = ei[i];
        if (v < 0 || v >= (long long)N) bad = 1;
    }
    __syncthreads();
    if (threadIdx.x == 0) g_is64 = bad ? 0 : 1;
}

// ---------------------------------------------------------------------------
// g_buf0 = (1+eps)*x ; zero stats accumulators
__global__ void init_kernel(const float* __restrict__ x,
                            const float* __restrict__ eps, int total4) {
    int i = blockIdx.x * blockDim.x + threadIdx.x;
    float s = 1.0f + eps[0];
    if (i < total4) {
        float4 v = ((const float4*)x)[i];
        v.x *= s; v.y *= s; v.z *= s; v.w *= s;
        ((float4*)g_buf0)[i] = v;
    }
    if (blockIdx.x == 0 && threadIdx.x < 2 * D) {
        int p = threadIdx.x / D, c = threadIdx.x % D;
        g_sum[p][c] = 0.f;
        g_sq[p][c]  = 0.f;
    }
}

// ---------------------------------------------------------------------------
// One warp per edge: gather x[src] row, vector-reduce into g_buf0[dst].
__global__ void scatter_kernel(const float* __restrict__ x,
                               const void* __restrict__ ei_raw, int E) {
    int e = (blockIdx.x * blockDim.x + threadIdx.x) >> 5;
    if (e >= E) return;
    int lane = threadIdx.x & 31;
    long long s, d;
    if (g_is64) {
        const long long* p = (const long long*)ei_raw;
        s = p[e];
        d = p[E + e];
    } else {
        const int* p = (const int*)ei_raw;
        s = p[e];
        d = p[E + e];
    }
    float4 v = __ldg((const float4*)(x + s * D) + lane);
    float* addr = g_buf0 + d * D + (lane << 2);
    asm volatile("red.global.add.v4.f32 [%0], {%1,%2,%3,%4};"
                 :: "l"(addr), "f"(v.x), "f"(v.y), "f"(v.z), "f"(v.w)
                 : "memory");
}

// ---------------------------------------------------------------------------
// out[N,128] = op(A)[N,128] @ W[128,128] + bias, fused with:
//   - optional input normalization (normPhase >= 0): a = relu(a*scale+shift)
//   - BN stats (column sum/sumsq of output) into g_sum/g_sq[phase]
// One 128x128 tile per block, 256 threads, whole W + whole A tile in smem,
// single __syncthreads, packed f32x2 FMA (row pairs), 4x8 ull accumulators.
__global__ void __launch_bounds__(256, 1)
gemm_kernel(const float* __restrict__ A, const float* __restrict__ W,
            const float* __restrict__ bias, float* __restrict__ out,
            int N, int phase, int normPhase) {
    extern __shared__ __align__(16) float smem[];
    float* As = smem;             // As[k][row], k-major: As[k*128 + row]
    float* Bs = smem + D * D;     // Bs[k][col], row-major: Bs[k*128 + col]

    int tid = threadIdx.x;
    int tx = tid & 15;        // col group: cols tx*8 .. tx*8+7
    int ty = tid >> 4;        // row group: rows ty*8 .. ty*8+7
    int rowStart = blockIdx.x * BM;

    // --- Load whole A tile (128x128), transposed into As[k][row].
    // Mapping: row = t & 127 (consecutive within warp -> conflict-free STS),
    //          c4  = t >> 7 (k block).
#pragma unroll
    for (int l = 0; l < 16; l++) {
        int t   = tid + 256 * l;
        int row = t & 127;
        int c4  = t >> 7;          // 0..31
        int gr  = rowStart + row;
        float4 v = make_float4(0.f, 0.f, 0.f, 0.f);
        if (gr < N) v = __ldg((const float4*)(A + (size_t)gr * D) + c4);
        if (normPhase >= 0) {
            float4 sc = ((const float4*)g_scale[normPhase])[c4];
            float4 sh = ((const float4*)g_shift[normPhase])[c4];
            v.x = fmaxf(v.x * sc.x + sh.x, 0.f);
            v.y = fmaxf(v.y * sc.y + sh.y, 0.f);
            v.z = fmaxf(v.z * sc.z + sh.z, 0.f);
            v.w = fmaxf(v.w * sc.w + sh.w, 0.f);
        }
        As[(c4 * 4 + 0) * D + row] = v.x;
        As[(c4 * 4 + 1) * D + row] = v.y;
        As[(c4 * 4 + 2) * D + row] = v.z;
        As[(c4 * 4 + 3) * D + row] = v.w;
    }
    // --- Load whole W (128x128) row-major (coalesced, conflict-free).
#pragma unroll
    for (int l = 0; l < 16; l++) {
        int t   = tid + 256 * l;
        int row = t >> 5;
        int c4  = t & 31;
        *((float4*)&Bs[row * D + c4 * 4]) =
            __ldg((const float4*)(W + (size_t)row * D) + c4);
    }
    __syncthreads();

    // --- Mainloop: acc[i][j] holds row-pair (ty*8+2i, ty*8+2i+1) x col (tx*8+j)
    ull acc[4][8];
#pragma unroll
    for (int i = 0; i < 4; i++)
#pragma unroll
        for (int j = 0; j < 8; j++) acc[i][j] = 0ull;

#pragma unroll 4
    for (int kk = 0; kk < D; kk++) {
        ull a[4];
#pragma unroll
        for (int i = 0; i < 4; i++)
            a[i] = *((const ull*)&As[kk * D + ty * 8 + 2 * i]);
        float4 b0 = *((const float4*)&Bs[kk * D + tx * 8]);
        float4 b1 = *((const float4*)&Bs[kk * D + tx * 8 + 4]);
        float bf[8] = {b0.x, b0.y, b0.z, b0.w, b1.x, b1.y, b1.z, b1.w};
        ull bb[8];
#pragma unroll
        for (int j = 0; j < 8; j++) bb[j] = pack2(bf[j], bf[j]);
#pragma unroll
        for (int i = 0; i < 4; i++)
#pragma unroll
            for (int j = 0; j < 8; j++) fma2(acc[i][j], a[i], bb[j]);
    }

    // --- Epilogue: bias, store, column stats from registers
    float4 bb0 = ((const float4*)bias)[tx * 2];
    float4 bb1 = ((const float4*)bias)[tx * 2 + 1];
    float bcol[8] = {bb0.x, bb0.y, bb0.z, bb0.w, bb1.x, bb1.y, bb1.z, bb1.w};
    float s[8], q[8];
#pragma unroll
    for (int j = 0; j < 8; j++) { s[j] = 0.f; q[j] = 0.f; }

#pragma unroll
    for (int i = 0; i < 4; i++) {
#pragma unroll
        for (int half = 0; half < 2; half++) {
            int gr = rowStart + ty * 8 + 2 * i + half;
            if (gr < N) {
                float h[8];
#pragma unroll
                for (int j = 0; j < 8; j++) {
                    float lo, hi;
                    unpack2(acc[i][j], lo, hi);
                    h[j] = (half ? hi : lo) + bcol[j];
                    s[j] += h[j];
                    q[j] += h[j] * h[j];
                }
                float* o = out + (size_t)gr * D + tx * 8;
                *((float4*)o)       = make_float4(h[0], h[1], h[2], h[3]);
                *((float4*)(o + 4)) = make_float4(h[4], h[5], h[6], h[7]);
            }
        }
    }
    // halve atomic count: combine across ty parity (lane xor 16)
#pragma unroll
    for (int j = 0; j < 8; j++) {
        s[j] += __shfl_xor_sync(0xffffffffu, s[j], 16);
        q[j] += __shfl_xor_sync(0xffffffffu, q[j], 16);
    }
    if ((ty & 1) == 0) {
#pragma unroll
        for (int j = 0; j < 8; j++) {
            atomicAdd(&g_sum[phase][tx * 8 + j], s[j]);
            atomicAdd(&g_sq[phase][tx * 8 + j],  q[j]);
        }
    }
}

// ---------------------------------------------------------------------------
__global__ void finalize_kernel(int phase, const float* __restrict__ g,
                                const float* __restrict__ beta, float invN) {
    int c = threadIdx.x;
    float mu  = g_sum[phase][c] * invN;
    float var = g_sq[phase][c] * invN - mu * mu;
    float inv = rsqrtf(var + 1e-5f);
    float sc  = g[c] * inv;
    g_scale[phase][c] = sc;
    g_shift[phase][c] = beta[c] - mu * sc;
}

// ---------------------------------------------------------------------------
// out = relu(h*scale + shift)  (final layer -> d_out)
__global__ void norm_kernel(const float* __restrict__ h, int phase,
                            float* __restrict__ extout, int total4) {
    int i = blockIdx.x * blockDim.x + threadIdx.x;
    if (i >= total4) return;
    int c4 = i & 31;
    float4 v  = ((const float4*)h)[i];
    float4 sc = ((const float4*)g_scale[phase])[c4];
    float4 sh = ((const float4*)g_shift[phase])[c4];
    float4 o;
    o.x = fmaxf(v.x * sc.x + sh.x, 0.f);
    o.y = fmaxf(v.y * sc.y + sh.y, 0.f);
    o.z = fmaxf(v.z * sc.z + sh.z, 0.f);
    o.w = fmaxf(v.w * sc.w + sh.w, 0.f);
    ((float4*)extout)[i] = o;
}

// ---------------------------------------------------------------------------
extern "C" void kernel_launch(void* const* d_in, const int* in_sizes, int n_in,
                              void* d_out, int out_size) {
    const float* x   = (const float*)d_in[0];
    const void*  ei  = d_in[1];
    const float* eps = (const float*)d_in[2];
    const float* W1  = (const float*)d_in[3];
    const float* b1  = (const float*)d_in[4];
    const float* g1  = (const float*)d_in[5];
    const float* be1 = (const float*)d_in[6];
    const float* W2  = (const float*)d_in[7];
    const float* b2  = (const float*)d_in[8];
    const float* g2  = (const float*)d_in[9];
    const float* be2 = (const float*)d_in[10];

    int N = in_sizes[0] / D;
    int E = in_sizes[1] / 2;
    int total4 = N * (D / 4);
    const int TB = 256;

    float* buf0;
    float* buf1;
    cudaGetSymbolAddress((void**)&buf0, g_buf0);
    cudaGetSymbolAddress((void**)&buf1, g_buf1);

    cudaFuncSetAttribute(gemm_kernel,
                         cudaFuncAttributeMaxDynamicSharedMemorySize,
                         SMEM_BYTES);

    detect_kernel<<<1, 256>>>((const long long*)ei, E, N);
    init_kernel<<<(total4 + TB - 1) / TB, TB>>>(x, eps, total4);

    long long sthreads = (long long)E * 32;
    scatter_kernel<<<(unsigned)((sthreads + TB - 1) / TB), TB>>>(x, ei, E);

    int gblocks = (N + BM - 1) / BM;
    float invN = 1.0f / (float)N;

    // layer 1: h1 = g_buf0 @ W1 + b1  (stats fused)
    gemm_kernel<<<gblocks, 256, SMEM_BYTES>>>(buf0, W1, b1, buf1, N, 0, -1);
    finalize_kernel<<<1, D>>>(0, g1, be1, invN);
    // layer 2: h2 = relu(bn(h1)) @ W2 + b2  (norm of h1 fused into A-load)
    gemm_kernel<<<gblocks, 256, SMEM_BYTES>>>(buf1, W2, b2, buf0, N, 1, 0);
    finalize_kernel<<<1, D>>>(1, g2, be2, invN);
    // final: d_out = relu(bn(h2))
    norm_kernel<<<(total4 + TB - 1) / TB, TB>>>(buf0, 1, (float*)d_out, total4);
}

// round 5
// speedup vs baseline: 1.6470x; 1.5670x over previous
#include <cuda_runtime.h>

#define MAXN 50000
#define D 128
#define BM 64
#define BK 32

// Scratch (no cudaMalloc allowed)
__device__ float g_buf0[MAXN * D];   // aggregated input, later h2 raw
__device__ float g_buf1[MAXN * D];   // h1 raw
__device__ float g_sum[2][D];
__device__ float g_sq[2][D];
__device__ float g_scale[2][D];
__device__ float g_shift[2][D];
__device__ int   g_is64;

// ---------------------------------------------------------------------------
// Detect int64 vs int32 edge_index (JAX x64 ambiguity).
__global__ void detect_kernel(const long long* __restrict__ ei, int E, int N) {
    __shared__ int bad;
    if (threadIdx.x == 0) bad = 0;
    __syncthreads();
    int M = min(E, 4096);
    for (int i = threadIdx.x; i < M; i += blockDim.x) {
        long long v = ei[i];
        if (v < 0 || v >= (long long)N) bad = 1;
    }
    __syncthreads();
    if (threadIdx.x == 0) g_is64 = bad ? 0 : 1;
}

// ---------------------------------------------------------------------------
// g_buf0 = (1+eps)*x ; zero stats accumulators
__global__ void init_kernel(const float* __restrict__ x,
                            const float* __restrict__ eps, int total4) {
    int i = blockIdx.x * blockDim.x + threadIdx.x;
    float s = 1.0f + eps[0];
    if (i < total4) {
        float4 v = ((const float4*)x)[i];
        v.x *= s; v.y *= s; v.z *= s; v.w *= s;
        ((float4*)g_buf0)[i] = v;
    }
    if (blockIdx.x == 0 && threadIdx.x < 2 * D) {
        int p = threadIdx.x / D, c = threadIdx.x % D;
        g_sum[p][c] = 0.f;
        g_sq[p][c]  = 0.f;
    }
}

// ---------------------------------------------------------------------------
// One warp per edge: gather x[src] row, vector-reduce into g_buf0[dst].
__global__ void scatter_kernel(const float* __restrict__ x,
                               const void* __restrict__ ei_raw, int E) {
    int e = (blockIdx.x * blockDim.x + threadIdx.x) >> 5;
    if (e >= E) return;
    int lane = threadIdx.x & 31;
    long long s, d;
    if (g_is64) {
        const long long* p = (const long long*)ei_raw;
        s = p[e];
        d = p[E + e];
    } else {
        const int* p = (const int*)ei_raw;
        s = p[e];
        d = p[E + e];
    }
    float4 v = __ldg((const float4*)(x + s * D) + lane);
    float* addr = g_buf0 + d * D + (lane << 2);
    asm volatile("red.global.add.v4.f32 [%0], {%1,%2,%3,%4};"
                 :: "l"(addr), "f"(v.x), "f"(v.y), "f"(v.z), "f"(v.w)
                 : "memory");
}

// ---------------------------------------------------------------------------
// out[N,128] = op(A)[N,128] @ W[128,128] + bias, fused with:
//   - optional input normalization (normPhase >= 0): a = relu(a*scale+shift)
//   - BN stats (column sum/sumsq of output) into g_sum/g_sq[phase]
// Round-1 structure: BM=64, BK=32, 256 threads, 4x8 per thread, plain FFMA.
// __launch_bounds__(256,4) -> 64-reg cap -> 4 blocks/SM (50% occupancy).
__global__ void __launch_bounds__(256, 4)
gemm_kernel(const float* __restrict__ A, const float* __restrict__ W,
            const float* __restrict__ bias, float* __restrict__ out,
            int N, int phase, int normPhase) {
    __shared__ __align__(16) float As[BK][BM];
    __shared__ __align__(16) float Bs[BK][D];

    int tid = threadIdx.x;
    int tx = tid & 15;       // col group: cols tx*8 .. tx*8+7
    int ty = tid >> 4;       // row group: rows ty + 16*i, i<4
    int rowStart = blockIdx.x * BM;

    float acc[4][8];
#pragma unroll
    for (int i = 0; i < 4; i++)
#pragma unroll
        for (int j = 0; j < 8; j++) acc[i][j] = 0.f;

    for (int kc = 0; kc < D; kc += BK) {
        // A tile (64x32 = 512 float4, 2/thread), transpose into As
#pragma unroll
        for (int l = 0; l < 2; l++) {
            int t   = tid + 256 * l;
            int row = t >> 3;
            int c4  = t & 7;
            int gr  = rowStart + row;
            float4 v = make_float4(0.f, 0.f, 0.f, 0.f);
            if (gr < N) v = ((const float4*)(A + (size_t)gr * D + kc))[c4];
            if (normPhase >= 0) {
                float4 sc = ((const float4*)g_scale[normPhase])[(kc >> 2) + c4];
                float4 sh = ((const float4*)g_shift[normPhase])[(kc >> 2) + c4];
                v.x = fmaxf(v.x * sc.x + sh.x, 0.f);
                v.y = fmaxf(v.y * sc.y + sh.y, 0.f);
                v.z = fmaxf(v.z * sc.z + sh.z, 0.f);
                v.w = fmaxf(v.w * sc.w + sh.w, 0.f);
            }
            As[c4 * 4 + 0][row] = v.x;
            As[c4 * 4 + 1][row] = v.y;
            As[c4 * 4 + 2][row] = v.z;
            As[c4 * 4 + 3][row] = v.w;
        }
        // B tile (32x128 = 1024 float4, 4/thread)
#pragma unroll
        for (int l = 0; l < 4; l++) {
            int t   = tid + 256 * l;
            int row = t >> 5;
            int c4  = t & 31;
            *((float4*)&Bs[row][c4 * 4]) =
                ((const float4*)(W + (size_t)(kc + row) * D))[c4];
        }
        __syncthreads();

#pragma unroll
        for (int kk = 0; kk < BK; kk++) {
            float a[4];
#pragma unroll
            for (int i = 0; i < 4; i++) a[i] = As[kk][ty + 16 * i];
            float4 b0 = *((const float4*)&Bs[kk][tx * 8]);
            float4 b1 = *((const float4*)&Bs[kk][tx * 8 + 4]);
            float b[8] = {b0.x, b0.y, b0.z, b0.w, b1.x, b1.y, b1.z, b1.w};
#pragma unroll
            for (int i = 0; i < 4; i++)
#pragma unroll
                for (int j = 0; j < 8; j++)
                    acc[i][j] = fmaf(a[i], b[j], acc[i][j]);
        }
        __syncthreads();
    }

    // Epilogue: bias, store, per-thread column stats
    float4 bb0 = ((const float4*)bias)[tx * 2];
    float4 bb1 = ((const float4*)bias)[tx * 2 + 1];
    float bcol[8] = {bb0.x, bb0.y, bb0.z, bb0.w, bb1.x, bb1.y, bb1.z, bb1.w};
    float s[8], q[8];
#pragma unroll
    for (int j = 0; j < 8; j++) { s[j] = 0.f; q[j] = 0.f; }

#pragma unroll
    for (int i = 0; i < 4; i++) {
        int gr = rowStart + ty + 16 * i;
        if (gr < N) {
            float h[8];
#pragma unroll
            for (int j = 0; j < 8; j++) {
                h[j] = acc[i][j] + bcol[j];
                s[j] += h[j];
                q[j] += h[j] * h[j];
            }
            float* o = out + (size_t)gr * D + tx * 8;
            *((float4*)o)       = make_float4(h[0], h[1], h[2], h[3]);
            *((float4*)(o + 4)) = make_float4(h[4], h[5], h[6], h[7]);
        }
    }

    // Combine ty-parity pairs (lane xor 16), stage per-warp partials in smem,
    // then one atomicAdd per (array, column) per block.
#pragma unroll
    for (int j = 0; j < 8; j++) {
        s[j] += __shfl_xor_sync(0xffffffffu, s[j], 16);
        q[j] += __shfl_xor_sync(0xffffffffu, q[j], 16);
    }
    float* red = &As[0][0];   // reuse 8KB As as [2][8][128] staging
    __syncthreads();
    if ((ty & 1) == 0) {
        int w = tid >> 5;
#pragma unroll
        for (int j = 0; j < 8; j++) {
            red[w * D + tx * 8 + j]        = s[j];
            red[1024 + w * D + tx * 8 + j] = q[j];
        }
    }
    __syncthreads();
    {
        int arr = tid >> 7;            // 0 = sum, 1 = sq
        int col = tid & 127;
        float a = 0.f;
#pragma unroll
        for (int w = 0; w < 8; w++) a += red[arr * 1024 + w * D + col];
        float* dstp = arr ? &g_sq[phase][col] : &g_sum[phase][col];
        atomicAdd(dstp, a);
    }
}

// ---------------------------------------------------------------------------
__global__ void finalize_kernel(int phase, const float* __restrict__ g,
                                const float* __restrict__ beta, float invN) {
    int c = threadIdx.x;
    float mu  = g_sum[phase][c] * invN;
    float var = g_sq[phase][c] * invN - mu * mu;
    float inv = rsqrtf(var + 1e-5f);
    float sc  = g[c] * inv;
    g_scale[phase][c] = sc;
    g_shift[phase][c] = beta[c] - mu * sc;
}

// ---------------------------------------------------------------------------
// out = relu(h*scale + shift)  (final layer -> d_out)
__global__ void norm_kernel(const float* __restrict__ h, int phase,
                            float* __restrict__ extout, int total4) {
    int i = blockIdx.x * blockDim.x + threadIdx.x;
    if (i >= total4) return;
    int c4 = i & 31;
    float4 v  = ((const float4*)h)[i];
    float4 sc = ((const float4*)g_scale[phase])[c4];
    float4 sh = ((const float4*)g_shift[phase])[c4];
    float4 o;
    o.x = fmaxf(v.x * sc.x + sh.x, 0.f);
    o.y = fmaxf(v.y * sc.y + sh.y, 0.f);
    o.z = fmaxf(v.z * sc.z + sh.z, 0.f);
    o.w = fmaxf(v.w * sc.w + sh.w, 0.f);
    ((float4*)extout)[i] = o;
}

// ---------------------------------------------------------------------------
extern "C" void kernel_launch(void* const* d_in, const int* in_sizes, int n_in,
                              void* d_out, int out_size) {
    const float* x   = (const float*)d_in[0];
    const void*  ei  = d_in[1];
    const float* eps = (const float*)d_in[2];
    const float* W1  = (const float*)d_in[3];
    const float* b1  = (const float*)d_in[4];
    const float* g1  = (const float*)d_in[5];
    const float* be1 = (const float*)d_in[6];
    const float* W2  = (const float*)d_in[7];
    const float* b2  = (const float*)d_in[8];
    const float* g2  = (const float*)d_in[9];
    const float* be2 = (const float*)d_in[10];

    int N = in_sizes[0] / D;
    int E = in_sizes[1] / 2;
    int total4 = N * (D / 4);
    const int TB = 256;

    float* buf0;
    float* buf1;
    cudaGetSymbolAddress((void**)&buf0, g_buf0);
    cudaGetSymbolAddress((void**)&buf1, g_buf1);

    detect_kernel<<<1, 256>>>((const long long*)ei, E, N);
    init_kernel<<<(total4 + TB - 1) / TB, TB>>>(x, eps, total4);

    long long sthreads = (long long)E * 32;
    scatter_kernel<<<(unsigned)((sthreads + TB - 1) / TB), TB>>>(x, ei, E);

    int gblocks = (N + BM - 1) / BM;
    float invN = 1.0f / (float)N;

    // layer 1: h1 = g_buf0 @ W1 + b1  (stats fused)
    gemm_kernel<<<gblocks, 256>>>(buf0, W1, b1, buf1, N, 0, -1);
    finalize_kernel<<<1, D>>>(0, g1, be1, invN);
    // layer 2: h2 = relu(bn(h1)) @ W2 + b2  (norm of h1 fused into A-load)
    gemm_kernel<<<gblocks, 256>>>(buf1, W2, b2, buf0, N, 1, 0);
    finalize_kernel<<<1, D>>>(1, g2, be2, invN);
    // final: d_out = relu(bn(h2))
    norm_kernel<<<(total4 + TB - 1) / TB, TB>>>(buf0, 1, (float*)d_out, total4);
}

// round 7
// speedup vs baseline: 2.6349x; 1.5998x over previous
#include <cuda_runtime.h>
#include <cuda_bf16.h>
#include <cstdint>

#define MAXN 50000
#define D 128
#define TSTRIDE 136                    /* padded tile row stride in bf16 */
#define TROWB   (TSTRIDE * 2)          /* 272 bytes per tile row */
#define TILE_BYTES (128 * TROWB)       /* 34816 */

// ---- dynamic smem layout (bytes) ----
#define A_HI 0
#define A_LO (A_HI + TILE_BYTES)
#define W_HI (A_LO + TILE_BYTES)
#define W_LO (W_HI + TILE_BYTES)
#define RED_OFF (W_LO + TILE_BYTES)    /* 139264: 512 floats */
#define SMEM_TOTAL (RED_OFF + 2048)    /* 141312 */

// Scratch (no cudaMalloc allowed)
__device__ float g_buf0[MAXN * D];
__device__ float g_buf1[MAXN * D];
__device__ __nv_bfloat16 g_Whi[2][D * D];   // W^T split-high, [n][k]
__device__ __nv_bfloat16 g_Wlo[2][D * D];   // W^T split-low,  [n][k]
__device__ float g_sum[2][D];
__device__ float g_sq[2][D];
__device__ float g_scale[2][D];
__device__ float g_shift[2][D];
__device__ int   g_is64;

// ---------------------------------------------------------------------------
static __device__ __forceinline__ uint32_t pack_bf2(__nv_bfloat16 a, __nv_bfloat16 b) {
    return (uint32_t)__bfloat16_as_ushort(a) |
           ((uint32_t)__bfloat16_as_ushort(b) << 16);
}
static __device__ __forceinline__ void mma16816(float* c, const uint32_t* a,
                                                const uint32_t* b) {
    asm volatile(
        "mma.sync.aligned.m16n8k16.row.col.f32.bf16.bf16.f32 "
        "{%0,%1,%2,%3}, {%4,%5,%6,%7}, {%8,%9}, {%0,%1,%2,%3};"
        : "+f"(c[0]), "+f"(c[1]), "+f"(c[2]), "+f"(c[3])
        : "r"(a[0]), "r"(a[1]), "r"(a[2]), "r"(a[3]), "r"(b[0]), "r"(b[1]));
}

// ---------------------------------------------------------------------------
// Detect int64 vs int32 edge_index (JAX x64 ambiguity).
__global__ void detect_kernel(const long long* __restrict__ ei, int E, int N) {
    __shared__ int bad;
    if (threadIdx.x == 0) bad = 0;
    __syncthreads();
    int M = min(E, 4096);
    for (int i = threadIdx.x; i < M; i += blockDim.x) {
        long long v = ei[i];
        if (v < 0 || v >= (long long)N) bad = 1;
    }
    __syncthreads();
    if (threadIdx.x == 0) g_is64 = bad ? 0 : 1;
}

// ---------------------------------------------------------------------------
// g_buf0 = (1+eps)*x ; zero stats accumulators
__global__ void init_kernel(const float* __restrict__ x,
                            const float* __restrict__ eps, int total4) {
    int i = blockIdx.x * blockDim.x + threadIdx.x;
    float s = 1.0f + eps[0];
    if (i < total4) {
        float4 v = ((const float4*)x)[i];
        v.x *= s; v.y *= s; v.z *= s; v.w *= s;
        ((float4*)g_buf0)[i] = v;
    }
    if (blockIdx.x == 0 && threadIdx.x < 2 * D) {
        int p = threadIdx.x / D, c = threadIdx.x % D;
        g_sum[p][c] = 0.f;
        g_sq[p][c]  = 0.f;
    }
}

// ---------------------------------------------------------------------------
// Split W (transposed to [n][k]) into bf16 hi/lo for both layers.
__global__ void prep_w(const float* __restrict__ W1, const float* __restrict__ W2) {
    int idx = blockIdx.x * blockDim.x + threadIdx.x;
    if (idx >= 2 * D * D) return;
    int L = idx >> 14;
    int r = idx & 16383;
    int n = r >> 7, k = r & 127;
    const float* W = L ? W2 : W1;
    float w = W[k * D + n];
    __nv_bfloat16 hi = __float2bfloat16(w);
    float lof = w - __bfloat162float(hi);
    g_Whi[L][n * D + k] = hi;
    g_Wlo[L][n * D + k] = __float2bfloat16(lof);
}

// ---------------------------------------------------------------------------
// One warp per edge: gather x[src] row, vector-reduce into g_buf0[dst].
__global__ void scatter_kernel(const float* __restrict__ x,
                               const void* __restrict__ ei_raw, int E) {
    int e = (blockIdx.x * blockDim.x + threadIdx.x) >> 5;
    if (e >= E) return;
    int lane = threadIdx.x & 31;
    long long s, d;
    if (g_is64) {
        const long long* p = (const long long*)ei_raw;
        s = p[e];
        d = p[E + e];
    } else {
        const int* p = (const int*)ei_raw;
        s = p[e];
        d = p[E + e];
    }
    float4 v = __ldg((const float4*)(x + s * D) + lane);
    float* addr = g_buf0 + d * D + (lane << 2);
    asm volatile("red.global.add.v4.f32 [%0], {%1,%2,%3,%4};"
                 :: "l"(addr), "f"(v.x), "f"(v.y), "f"(v.z), "f"(v.w)
                 : "memory");
}

// ---------------------------------------------------------------------------
// Tensor-core GEMM via mma.sync (HMMA): out = op(A) @ W^T + bias.
// Split-bf16: D = Ahi*Whi + Ahi*Wlo + Alo*Whi, fp32 register accumulators.
// 256 threads = 8 warps (2x4), warp tile 64x32, block tile 128x128, K=128.
// Fused: optional norm+relu on A (normPhase>=0); BN stats in epilogue.
__global__ void __launch_bounds__(256)
gemm_tc(const float* __restrict__ A, int layer, const float* __restrict__ bias,
        float* __restrict__ out, int N, int phase, int normPhase) {
    extern __shared__ char smem[];
    int tid = threadIdx.x, wid = tid >> 5, lane = tid & 31;
    int gq = lane >> 2;          // groupID 0..7
    int q  = lane & 3;           // threadID-in-group 0..3
    int warpM = wid >> 2;        // 0..1
    int warpN = wid & 3;         // 0..3
    int rowStart = blockIdx.x * 128;

    const __nv_bfloat16* Whi = g_Whi[layer];
    const __nv_bfloat16* Wlo = g_Wlo[layer];

    // --- A tile: load fp32, (norm+relu), split bf16 hi/lo, padded store.
#pragma unroll
    for (int l = 0; l < 16; l++) {
        int idx = tid + 256 * l;
        int row = idx >> 5, c4 = idx & 31;
        int gr = rowStart + row;
        float4 v = make_float4(0.f, 0.f, 0.f, 0.f);
        if (gr < N) v = __ldg((const float4*)(A + (size_t)gr * D) + c4);
        if (normPhase >= 0) {
            float4 sc = ((const float4*)g_scale[normPhase])[c4];
            float4 sh = ((const float4*)g_shift[normPhase])[c4];
            v.x = fmaxf(fmaf(v.x, sc.x, sh.x), 0.f);
            v.y = fmaxf(fmaf(v.y, sc.y, sh.y), 0.f);
            v.z = fmaxf(fmaf(v.z, sc.z, sh.z), 0.f);
            v.w = fmaxf(fmaf(v.w, sc.w, sh.w), 0.f);
        }
        __nv_bfloat16 hx = __float2bfloat16(v.x), hy = __float2bfloat16(v.y);
        __nv_bfloat16 hz = __float2bfloat16(v.z), hw = __float2bfloat16(v.w);
        uint2 hi2, lo2;
        hi2.x = pack_bf2(hx, hy);
        hi2.y = pack_bf2(hz, hw);
        lo2.x = pack_bf2(__float2bfloat16(v.x - __bfloat162float(hx)),
                         __float2bfloat16(v.y - __bfloat162float(hy)));
        lo2.y = pack_bf2(__float2bfloat16(v.z - __bfloat162float(hz)),
                         __float2bfloat16(v.w - __bfloat162float(hw)));
        uint32_t off = row * TROWB + c4 * 8;
        *(uint2*)(smem + A_HI + off) = hi2;
        *(uint2*)(smem + A_LO + off) = lo2;
    }
    // --- W tiles: pre-split bf16 [n][k] -> padded smem.
#pragma unroll
    for (int l = 0; l < 16; l++) {
        int idx = tid + 256 * l;
        int n = idx >> 5, c4 = idx & 31;
        uint32_t off = n * TROWB + c4 * 8;
        *(uint2*)(smem + W_HI + off) = *(const uint2*)(Whi + n * D + c4 * 4);
        *(uint2*)(smem + W_LO + off) = *(const uint2*)(Wlo + n * D + c4 * 4);
    }
    __syncthreads();

    float acc[4][4][4];
#pragma unroll
    for (int mt = 0; mt < 4; mt++)
#pragma unroll
        for (int nt = 0; nt < 4; nt++)
#pragma unroll
            for (int r = 0; r < 4; r++) acc[mt][nt][r] = 0.f;

#pragma unroll 1
    for (int pass = 0; pass < 3; pass++) {
        const char* aBase = smem + ((pass == 2) ? A_LO : A_HI);
        const char* bBase = smem + ((pass == 1) ? W_LO : W_HI);
#pragma unroll
        for (int ks = 0; ks < 8; ks++) {
            int kb = ks * 32 + q * 4;    // byte offset of k-word in row
            uint32_t a[4][4], b[4][2];
#pragma unroll
            for (int mt = 0; mt < 4; mt++) {
                const char* ap = aBase + (warpM * 64 + mt * 16 + gq) * TROWB + kb;
                a[mt][0] = *(const uint32_t*)(ap);
                a[mt][1] = *(const uint32_t*)(ap + 8 * TROWB);
                a[mt][2] = *(const uint32_t*)(ap + 16);
                a[mt][3] = *(const uint32_t*)(ap + 8 * TROWB + 16);
            }
#pragma unroll
            for (int nt = 0; nt < 4; nt++) {
                const char* bp = bBase + (warpN * 32 + nt * 8 + gq) * TROWB + kb;
                b[nt][0] = *(const uint32_t*)(bp);
                b[nt][1] = *(const uint32_t*)(bp + 16);
            }
#pragma unroll
            for (int mt = 0; mt < 4; mt++)
#pragma unroll
                for (int nt = 0; nt < 4; nt++)
                    mma16816(acc[mt][nt], a[mt], b[nt]);
        }
    }

    // --- Epilogue: bias, store, BN stats.
    float s[4][2], qs[4][2];
#pragma unroll
    for (int nt = 0; nt < 4; nt++)
        s[nt][0] = s[nt][1] = qs[nt][0] = qs[nt][1] = 0.f;

#pragma unroll
    for (int nt = 0; nt < 4; nt++) {
        int cbase = warpN * 32 + nt * 8 + q * 2;
        float b0 = __ldg(&bias[cbase]), b1 = __ldg(&bias[cbase + 1]);
#pragma unroll
        for (int mt = 0; mt < 4; mt++) {
            int r0 = rowStart + warpM * 64 + mt * 16 + gq;
            int r1 = r0 + 8;
            float h0 = acc[mt][nt][0] + b0, h1 = acc[mt][nt][1] + b1;
            float h2 = acc[mt][nt][2] + b0, h3 = acc[mt][nt][3] + b1;
            if (r0 < N) {
                *(float2*)(out + (size_t)r0 * D + cbase) = make_float2(h0, h1);
                s[nt][0] += h0; s[nt][1] += h1;
                qs[nt][0] += h0 * h0; qs[nt][1] += h1 * h1;
            }
            if (r1 < N) {
                *(float2*)(out + (size_t)r1 * D + cbase) = make_float2(h2, h3);
                s[nt][0] += h2; s[nt][1] += h3;
                qs[nt][0] += h2 * h2; qs[nt][1] += h3 * h3;
            }
        }
    }
    // reduce across groupID lanes (same columns): xor 4, 8, 16
#pragma unroll
    for (int m = 4; m <= 16; m <<= 1)
#pragma unroll
        for (int nt = 0; nt < 4; nt++) {
            s[nt][0]  += __shfl_xor_sync(0xffffffffu, s[nt][0],  m);
            s[nt][1]  += __shfl_xor_sync(0xffffffffu, s[nt][1],  m);
            qs[nt][0] += __shfl_xor_sync(0xffffffffu, qs[nt][0], m);
            qs[nt][1] += __shfl_xor_sync(0xffffffffu, qs[nt][1], m);
        }
    float* red = (float*)(smem + RED_OFF);     // [2][8 warps][32]
    __syncthreads();
    if (lane < 4) {
#pragma unroll
        for (int nt = 0; nt < 4; nt++) {
            red[wid * 32 + nt * 8 + lane * 2]           = s[nt][0];
            red[wid * 32 + nt * 8 + lane * 2 + 1]       = s[nt][1];
            red[256 + wid * 32 + nt * 8 + lane * 2]     = qs[nt][0];
            red[256 + wid * 32 + nt * 8 + lane * 2 + 1] = qs[nt][1];
        }
    }
    __syncthreads();
    if (tid < 128) {
        atomicAdd(&g_sum[phase][tid], red[tid] + red[tid + 128]);
    } else {
        int c = tid - 128;
        atomicAdd(&g_sq[phase][c], red[256 + c] + red[256 + c + 128]);
    }
}

// ---------------------------------------------------------------------------
__global__ void finalize_kernel(int phase, const float* __restrict__ g,
                                const float* __restrict__ beta, float invN) {
    int c = threadIdx.x;
    float mu  = g_sum[phase][c] * invN;
    float var = g_sq[phase][c] * invN - mu * mu;
    float inv = rsqrtf(var + 1e-5f);
    float sc  = g[c] * inv;
    g_scale[phase][c] = sc;
    g_shift[phase][c] = beta[c] - mu * sc;
}

// ---------------------------------------------------------------------------
// out = relu(h*scale + shift)  (final layer -> d_out)
__global__ void norm_kernel(const float* __restrict__ h, int phase,
                            float* __restrict__ extout, int total4) {
    int i = blockIdx.x * blockDim.x + threadIdx.x;
    if (i >= total4) return;
    int c4 = i & 31;
    float4 v  = ((const float4*)h)[i];
    float4 sc = ((const float4*)g_scale[phase])[c4];
    float4 sh = ((const float4*)g_shift[phase])[c4];
    float4 o;
    o.x = fmaxf(v.x * sc.x + sh.x, 0.f);
    o.y = fmaxf(v.y * sc.y + sh.y, 0.f);
    o.z = fmaxf(v.z * sc.z + sh.z, 0.f);
    o.w = fmaxf(v.w * sc.w + sh.w, 0.f);
    ((float4*)extout)[i] = o;
}

// ---------------------------------------------------------------------------
extern "C" void kernel_launch(void* const* d_in, const int* in_sizes, int n_in,
                              void* d_out, int out_size) {
    const float* x   = (const float*)d_in[0];
    const void*  ei  = d_in[1];
    const float* eps = (const float*)d_in[2];
    const float* W1  = (const float*)d_in[3];
    const float* b1  = (const float*)d_in[4];
    const float* g1  = (const float*)d_in[5];
    const float* be1 = (const float*)d_in[6];
    const float* W2  = (const float*)d_in[7];
    const float* b2  = (const float*)d_in[8];
    const float* g2  = (const float*)d_in[9];
    const float* be2 = (const float*)d_in[10];

    int N = in_sizes[0] / D;
    int E = in_sizes[1] / 2;
    int total4 = N * (D / 4);
    const int TB = 256;

    float* buf0;
    float* buf1;
    cudaGetSymbolAddress((void**)&buf0, g_buf0);
    cudaGetSymbolAddress((void**)&buf1, g_buf1);

    cudaFuncSetAttribute(gemm_tc, cudaFuncAttributeMaxDynamicSharedMemorySize,
                         SMEM_TOTAL);

    detect_kernel<<<1, 256>>>((const long long*)ei, E, N);
    init_kernel<<<(total4 + TB - 1) / TB, TB>>>(x, eps, total4);
    prep_w<<<(2 * D * D + TB - 1) / TB, TB>>>(W1, W2);

    long long sthreads = (long long)E * 32;
    scatter_kernel<<<(unsigned)((sthreads + TB - 1) / TB), TB>>>(x, ei, E);

    int gblocks = (N + 127) / 128;
    float invN = 1.0f / (float)N;

    // layer 1: h1 = g_buf0 @ W1 + b1 (stats fused)
    gemm_tc<<<gblocks, 256, SMEM_TOTAL>>>(buf0, 0, b1, buf1, N, 0, -1);
    finalize_kernel<<<1, D>>>(0, g1, be1, invN);
    // layer 2: h2 = relu(bn(h1)) @ W2 + b2 (norm fused into A loader)
    gemm_tc<<<gblocks, 256, SMEM_TOTAL>>>(buf1, 1, b2, buf0, N, 1, 0);
    finalize_kernel<<<1, D>>>(1, g2, be2, invN);
    // final: d_out = relu(bn(h2))
    norm_kernel<<<(total4 + TB - 1) / TB, TB>>>(buf0, 1, (float*)d_out, total4);
}

// round 8
// speedup vs baseline: 3.4955x; 1.3266x over previous
#include <cuda_runtime.h>
#include <cuda_bf16.h>
#include <cstdint>

#define MAXN 50000
#define MAXE 800000
#define D 128
#define TSTRIDE 136                    /* padded tile row stride in bf16 */
#define TROWB   (TSTRIDE * 2)          /* 272 bytes per tile row */
#define TILE_BYTES (128 * TROWB)       /* 34816 */

// ---- dynamic smem layout (bytes) ----
#define A_HI 0
#define A_LO (A_HI + TILE_BYTES)
#define W_HI (A_LO + TILE_BYTES)
#define W_LO (W_HI + TILE_BYTES)
#define RED_OFF (W_LO + TILE_BYTES)    /* 139264: 512 floats */
#define SMEM_TOTAL (RED_OFF + 2048)    /* 141312 */

// Scratch (no cudaMalloc allowed)
__device__ float g_buf0[MAXN * D];
__device__ float g_buf1[MAXN * D];
__device__ __nv_bfloat16 g_Whi[2][D * D];   // W^T split-high, [n][k]
__device__ __nv_bfloat16 g_Wlo[2][D * D];   // W^T split-low,  [n][k]
__device__ float g_sum[2][D];
__device__ float g_sq[2][D];
__device__ float g_scale[2][D];
__device__ float g_shift[2][D];
__device__ int   g_is64;
// CSR-by-dst machinery
__device__ int g_cnt[MAXN];
__device__ int g_off[MAXN + 1];
__device__ int g_bsum[256];
__device__ int g_srcSorted[MAXE];

// ---------------------------------------------------------------------------
static __device__ __forceinline__ uint32_t pack_bf2(__nv_bfloat16 a, __nv_bfloat16 b) {
    return (uint32_t)__bfloat16_as_ushort(a) |
           ((uint32_t)__bfloat16_as_ushort(b) << 16);
}
static __device__ __forceinline__ void mma16816(float* c, const uint32_t* a,
                                                const uint32_t* b) {
    asm volatile(
        "mma.sync.aligned.m16n8k16.row.col.f32.bf16.bf16.f32 "
        "{%0,%1,%2,%3}, {%4,%5,%6,%7}, {%8,%9}, {%0,%1,%2,%3};"
        : "+f"(c[0]), "+f"(c[1]), "+f"(c[2]), "+f"(c[3])
        : "r"(a[0]), "r"(a[1]), "r"(a[2]), "r"(a[3]), "r"(b[0]), "r"(b[1]));
}

// ---------------------------------------------------------------------------
// Detect int64 vs int32 edge_index (JAX x64 ambiguity).
__global__ void detect_kernel(const long long* __restrict__ ei, int E, int N) {
    __shared__ int bad;
    if (threadIdx.x == 0) bad = 0;
    __syncthreads();
    int M = min(E, 4096);
    for (int i = threadIdx.x; i < M; i += blockDim.x) {
        long long v = ei[i];
        if (v < 0 || v >= (long long)N) bad = 1;
    }
    __syncthreads();
    if (threadIdx.x == 0) g_is64 = bad ? 0 : 1;
}

// ---------------------------------------------------------------------------
// Zero per-node counters and stats accumulators.
__global__ void zero_kernel(int N) {
    int i = blockIdx.x * blockDim.x + threadIdx.x;
    if (i < N) g_cnt[i] = 0;
    if (i < 2 * D) {
        int p = i / D, c = i % D;
        g_sum[p][c] = 0.f;
        g_sq[p][c]  = 0.f;
    }
}

// ---------------------------------------------------------------------------
__global__ void hist_kernel(const void* __restrict__ ei_raw, int E) {
    int e = blockIdx.x * blockDim.x + threadIdx.x;
    if (e >= E) return;
    int d;
    if (g_is64) d = (int)((const long long*)ei_raw)[E + e];
    else        d = ((const int*)ei_raw)[E + e];
    atomicAdd(&g_cnt[d], 1);
}

// Per-chunk inclusive scan (256 elems per block).
__global__ void scan_block(int N) {
    __shared__ int sh[256];
    int t = threadIdx.x;
    int i = blockIdx.x * 256 + t;
    sh[t] = (i < N) ? g_cnt[i] : 0;
    __syncthreads();
#pragma unroll
    for (int dlt = 1; dlt < 256; dlt <<= 1) {
        int v = (t >= dlt) ? sh[t - dlt] : 0;
        __syncthreads();
        sh[t] += v;
        __syncthreads();
    }
    if (i < N) g_off[i + 1] = sh[t];
    if (t == 255) g_bsum[blockIdx.x] = sh[255];
}

// Exclusive scan of block sums (<=256 blocks).
__global__ void scan_top(int nb) {
    __shared__ int sh[256];
    int t = threadIdx.x;
    sh[t] = (t < nb) ? g_bsum[t] : 0;
    __syncthreads();
#pragma unroll
    for (int dlt = 1; dlt < 256; dlt <<= 1) {
        int v = (t >= dlt) ? sh[t - dlt] : 0;
        __syncthreads();
        sh[t] += v;
        __syncthreads();
    }
    g_bsum[t] = (t == 0) ? 0 : sh[t - 1];
}

// Add block offsets, reset cursors.
__global__ void scan_add(int N) {
    int i = blockIdx.x * 256 + threadIdx.x;
    if (i < N) {
        g_off[i + 1] += g_bsum[blockIdx.x];
        g_cnt[i] = 0;
    }
    if (i == 0) g_off[0] = 0;
}

// Bucket edges by dst.
__global__ void bucket_kernel(const void* __restrict__ ei_raw, int E) {
    int e = blockIdx.x * blockDim.x + threadIdx.x;
    if (e >= E) return;
    int s, d;
    if (g_is64) {
        const long long* p = (const long long*)ei_raw;
        s = (int)p[e]; d = (int)p[E + e];
    } else {
        const int* p = (const int*)ei_raw;
        s = p[e]; d = p[E + e];
    }
    int pos = g_off[d] + atomicAdd(&g_cnt[d], 1);
    g_srcSorted[pos] = s;
}

// ---------------------------------------------------------------------------
// One warp per node: g_buf0[n] = (1+eps)*x[n] + sum_{src in bucket(n)} x[src].
// No float atomics; gather with MLP=4.
__global__ void aggregate_kernel(const float* __restrict__ x,
                                 const float* __restrict__ eps, int N) {
    int warp = (blockIdx.x * blockDim.x + threadIdx.x) >> 5;
    if (warp >= N) return;
    int lane = threadIdx.x & 31;
    float sc = 1.0f + eps[0];
    float4 acc = __ldg((const float4*)(x + (size_t)warp * D) + lane);
    acc.x *= sc; acc.y *= sc; acc.z *= sc; acc.w *= sc;

    int beg = g_off[warp], end = g_off[warp + 1];
    for (int c = beg; c < end; c += 32) {
        int n = min(32, end - c);
        int myv = (c + lane < end) ? __ldg(&g_srcSorted[c + lane]) : 0;
        int j = 0;
        for (; j + 4 <= n; j += 4) {
            int s0 = __shfl_sync(0xffffffffu, myv, j);
            int s1 = __shfl_sync(0xffffffffu, myv, j + 1);
            int s2 = __shfl_sync(0xffffffffu, myv, j + 2);
            int s3 = __shfl_sync(0xffffffffu, myv, j + 3);
            float4 v0 = __ldg((const float4*)(x + (size_t)s0 * D) + lane);
            float4 v1 = __ldg((const float4*)(x + (size_t)s1 * D) + lane);
            float4 v2 = __ldg((const float4*)(x + (size_t)s2 * D) + lane);
            float4 v3 = __ldg((const float4*)(x + (size_t)s3 * D) + lane);
            acc.x += (v0.x + v1.x) + (v2.x + v3.x);
            acc.y += (v0.y + v1.y) + (v2.y + v3.y);
            acc.z += (v0.z + v1.z) + (v2.z + v3.z);
            acc.w += (v0.w + v1.w) + (v2.w + v3.w);
        }
        for (; j < n; j++) {
            int s0 = __shfl_sync(0xffffffffu, myv, j);
            float4 v0 = __ldg((const float4*)(x + (size_t)s0 * D) + lane);
            acc.x += v0.x; acc.y += v0.y; acc.z += v0.z; acc.w += v0.w;
        }
    }
    ((float4*)(g_buf0 + (size_t)warp * D))[lane] = acc;
}

// ---------------------------------------------------------------------------
// Split W (transposed to [n][k]) into bf16 hi/lo for both layers.
__global__ void prep_w(const float* __restrict__ W1, const float* __restrict__ W2) {
    int idx = blockIdx.x * blockDim.x + threadIdx.x;
    if (idx >= 2 * D * D) return;
    int L = idx >> 14;
    int r = idx & 16383;
    int n = r >> 7, k = r & 127;
    const float* W = L ? W2 : W1;
    float w = W[k * D + n];
    __nv_bfloat16 hi = __float2bfloat16(w);
    float lof = w - __bfloat162float(hi);
    g_Whi[L][n * D + k] = hi;
    g_Wlo[L][n * D + k] = __float2bfloat16(lof);
}

// ---------------------------------------------------------------------------
// Tensor-core GEMM via mma.sync (HMMA): out = op(A) @ W^T + bias.
// Split-bf16: D = Ahi*Whi + Ahi*Wlo + Alo*Whi, fp32 register accumulators.
// 256 threads = 8 warps (2x4), warp tile 64x32, block tile 128x128, K=128.
// Fused: optional norm+relu on A (normPhase>=0); BN stats in epilogue.
__global__ void __launch_bounds__(256)
gemm_tc(const float* __restrict__ A, int layer, const float* __restrict__ bias,
        float* __restrict__ out, int N, int phase, int normPhase) {
    extern __shared__ char smem[];
    int tid = threadIdx.x, wid = tid >> 5, lane = tid & 31;
    int gq = lane >> 2;          // groupID 0..7
    int q  = lane & 3;           // threadID-in-group 0..3
    int warpM = wid >> 2;        // 0..1
    int warpN = wid & 3;         // 0..3
    int rowStart = blockIdx.x * 128;

    const __nv_bfloat16* Whi = g_Whi[layer];
    const __nv_bfloat16* Wlo = g_Wlo[layer];

    // --- A tile: load fp32, (norm+relu), split bf16 hi/lo, padded store.
#pragma unroll
    for (int l = 0; l < 16; l++) {
        int idx = tid + 256 * l;
        int row = idx >> 5, c4 = idx & 31;
        int gr = rowStart + row;
        float4 v = make_float4(0.f, 0.f, 0.f, 0.f);
        if (gr < N) v = __ldg((const float4*)(A + (size_t)gr * D) + c4);
        if (normPhase >= 0) {
            float4 sc = ((const float4*)g_scale[normPhase])[c4];
            float4 sh = ((const float4*)g_shift[normPhase])[c4];
            v.x = fmaxf(fmaf(v.x, sc.x, sh.x), 0.f);
            v.y = fmaxf(fmaf(v.y, sc.y, sh.y), 0.f);
            v.z = fmaxf(fmaf(v.z, sc.z, sh.z), 0.f);
            v.w = fmaxf(fmaf(v.w, sc.w, sh.w), 0.f);
        }
        __nv_bfloat16 hx = __float2bfloat16(v.x), hy = __float2bfloat16(v.y);
        __nv_bfloat16 hz = __float2bfloat16(v.z), hw = __float2bfloat16(v.w);
        uint2 hi2, lo2;
        hi2.x = pack_bf2(hx, hy);
        hi2.y = pack_bf2(hz, hw);
        lo2.x = pack_bf2(__float2bfloat16(v.x - __bfloat162float(hx)),
                         __float2bfloat16(v.y - __bfloat162float(hy)));
        lo2.y = pack_bf2(__float2bfloat16(v.z - __bfloat162float(hz)),
                         __float2bfloat16(v.w - __bfloat162float(hw)));
        uint32_t off = row * TROWB + c4 * 8;
        *(uint2*)(smem + A_HI + off) = hi2;
        *(uint2*)(smem + A_LO + off) = lo2;
    }
    // --- W tiles: pre-split bf16 [n][k] -> padded smem.
#pragma unroll
    for (int l = 0; l < 16; l++) {
        int idx = tid + 256 * l;
        int n = idx >> 5, c4 = idx & 31;
        uint32_t off = n * TROWB + c4 * 8;
        *(uint2*)(smem + W_HI + off) = *(const uint2*)(Whi + n * D + c4 * 4);
        *(uint2*)(smem + W_LO + off) = *(const uint2*)(Wlo + n * D + c4 * 4);
    }
    __syncthreads();

    float acc[4][4][4];
#pragma unroll
    for (int mt = 0; mt < 4; mt++)
#pragma unroll
        for (int nt = 0; nt < 4; nt++)
#pragma unroll
            for (int r = 0; r < 4; r++) acc[mt][nt][r] = 0.f;

#pragma unroll 1
    for (int pass = 0; pass < 3; pass++) {
        const char* aBase = smem + ((pass == 2) ? A_LO : A_HI);
        const char* bBase = smem + ((pass == 1) ? W_LO : W_HI);
#pragma unroll
        for (int ks = 0; ks < 8; ks++) {
            int kb = ks * 32 + q * 4;    // byte offset of k-word in row
            uint32_t a[4][4], b[4][2];
#pragma unroll
            for (int mt = 0; mt < 4; mt++) {
                const char* ap = aBase + (warpM * 64 + mt * 16 + gq) * TROWB + kb;
                a[mt][0] = *(const uint32_t*)(ap);
                a[mt][1] = *(const uint32_t*)(ap + 8 * TROWB);
                a[mt][2] = *(const uint32_t*)(ap + 16);
                a[mt][3] = *(const uint32_t*)(ap + 8 * TROWB + 16);
            }
#pragma unroll
            for (int nt = 0; nt < 4; nt++) {
                const char* bp = bBase + (warpN * 32 + nt * 8 + gq) * TROWB + kb;
                b[nt][0] = *(const uint32_t*)(bp);
                b[nt][1] = *(const uint32_t*)(bp + 16);
            }
#pragma unroll
            for (int mt = 0; mt < 4; mt++)
#pragma unroll
                for (int nt = 0; nt < 4; nt++)
                    mma16816(acc[mt][nt], a[mt], b[nt]);
        }
    }

    // --- Epilogue: bias, store, BN stats.
    float s[4][2], qs[4][2];
#pragma unroll
    for (int nt = 0; nt < 4; nt++)
        s[nt][0] = s[nt][1] = qs[nt][0] = qs[nt][1] = 0.f;

#pragma unroll
    for (int nt = 0; nt < 4; nt++) {
        int cbase = warpN * 32 + nt * 8 + q * 2;
        float b0 = __ldg(&bias[cbase]), b1 = __ldg(&bias[cbase + 1]);
#pragma unroll
        for (int mt = 0; mt < 4; mt++) {
            int r0 = rowStart + warpM * 64 + mt * 16 + gq;
            int r1 = r0 + 8;
            float h0 = acc[mt][nt][0] + b0, h1 = acc[mt][nt][1] + b1;
            float h2 = acc[mt][nt][2] + b0, h3 = acc[mt][nt][3] + b1;
            if (r0 < N) {
                *(float2*)(out + (size_t)r0 * D + cbase) = make_float2(h0, h1);
                s[nt][0] += h0; s[nt][1] += h1;
                qs[nt][0] += h0 * h0; qs[nt][1] += h1 * h1;
            }
            if (r1 < N) {
                *(float2*)(out + (size_t)r1 * D + cbase) = make_float2(h2, h3);
                s[nt][0] += h2; s[nt][1] += h3;
                qs[nt][0] += h2 * h2; qs[nt][1] += h3 * h3;
            }
        }
    }
    // reduce across groupID lanes (same columns): xor 4, 8, 16
#pragma unroll
    for (int m = 4; m <= 16; m <<= 1)
#pragma unroll
        for (int nt = 0; nt < 4; nt++) {
            s[nt][0]  += __shfl_xor_sync(0xffffffffu, s[nt][0],  m);
            s[nt][1]  += __shfl_xor_sync(0xffffffffu, s[nt][1],  m);
            qs[nt][0] += __shfl_xor_sync(0xffffffffu, qs[nt][0], m);
            qs[nt][1] += __shfl_xor_sync(0xffffffffu, qs[nt][1], m);
        }
    float* red = (float*)(smem + RED_OFF);     // [2][8 warps][32]
    __syncthreads();
    if (lane < 4) {
#pragma unroll
        for (int nt = 0; nt < 4; nt++) {
            red[wid * 32 + nt * 8 + lane * 2]           = s[nt][0];
            red[wid * 32 + nt * 8 + lane * 2 + 1]       = s[nt][1];
            red[256 + wid * 32 + nt * 8 + lane * 2]     = qs[nt][0];
            red[256 + wid * 32 + nt * 8 + lane * 2 + 1] = qs[nt][1];
        }
    }
    __syncthreads();
    if (tid < 128) {
        atomicAdd(&g_sum[phase][tid], red[tid] + red[tid + 128]);
    } else {
        int c = tid - 128;
        atomicAdd(&g_sq[phase][c], red[256 + c] + red[256 + c + 128]);
    }
}

// ---------------------------------------------------------------------------
__global__ void finalize_kernel(int phase, const float* __restrict__ g,
                                const float* __restrict__ beta, float invN) {
    int c = threadIdx.x;
    float mu  = g_sum[phase][c] * invN;
    float var = g_sq[phase][c] * invN - mu * mu;
    float inv = rsqrtf(var + 1e-5f);
    float sc  = g[c] * inv;
    g_scale[phase][c] = sc;
    g_shift[phase][c] = beta[c] - mu * sc;
}

// ---------------------------------------------------------------------------
// out = relu(h*scale + shift)  (final layer -> d_out)
__global__ void norm_kernel(const float* __restrict__ h, int phase,
                            float* __restrict__ extout, int total4) {
    int i = blockIdx.x * blockDim.x + threadIdx.x;
    if (i >= total4) return;
    int c4 = i & 31;
    float4 v  = ((const float4*)h)[i];
    float4 sc = ((const float4*)g_scale[phase])[c4];
    float4 sh = ((const float4*)g_shift[phase])[c4];
    float4 o;
    o.x = fmaxf(v.x * sc.x + sh.x, 0.f);
    o.y = fmaxf(v.y * sc.y + sh.y, 0.f);
    o.z = fmaxf(v.z * sc.z + sh.z, 0.f);
    o.w = fmaxf(v.w * sc.w + sh.w, 0.f);
    ((float4*)extout)[i] = o;
}

// ---------------------------------------------------------------------------
extern "C" void kernel_launch(void* const* d_in, const int* in_sizes, int n_in,
                              void* d_out, int out_size) {
    const float* x   = (const float*)d_in[0];
    const void*  ei  = d_in[1];
    const float* eps = (const float*)d_in[2];
    const float* W1  = (const float*)d_in[3];
    const float* b1  = (const float*)d_in[4];
    const float* g1  = (const float*)d_in[5];
    const float* be1 = (const float*)d_in[6];
    const float* W2  = (const float*)d_in[7];
    const float* b2  = (const float*)d_in[8];
    const float* g2  = (const float*)d_in[9];
    const float* be2 = (const float*)d_in[10];

    int N = in_sizes[0] / D;
    int E = in_sizes[1] / 2;
    int total4 = N * (D / 4);
    const int TB = 256;

    float* buf0;
    float* buf1;
    cudaGetSymbolAddress((void**)&buf0, g_buf0);
    cudaGetSymbolAddress((void**)&buf1, g_buf1);

    cudaFuncSetAttribute(gemm_tc, cudaFuncAttributeMaxDynamicSharedMemorySize,
                         SMEM_TOTAL);

    int nblk = (N + 255) / 256;
    int eblk = (E + 255) / 256;

    detect_kernel<<<1, 256>>>((const long long*)ei, E, N);
    zero_kernel<<<nblk, 256>>>(N);
    prep_w<<<(2 * D * D + TB - 1) / TB, TB>>>(W1, W2);
    hist_kernel<<<eblk, 256>>>(ei, E);
    scan_block<<<nblk, 256>>>(N);
    scan_top<<<1, 256>>>(nblk);
    scan_add<<<nblk, 256>>>(N);
    bucket_kernel<<<eblk, 256>>>(ei, E);
    aggregate_kernel<<<(N * 32 + TB - 1) / TB, TB>>>(x, eps, N);

    int gblocks = (N + 127) / 128;
    float invN = 1.0f / (float)N;

    // layer 1: h1 = g_buf0 @ W1 + b1 (stats fused)
    gemm_tc<<<gblocks, 256, SMEM_TOTAL>>>(buf0, 0, b1, buf1, N, 0, -1);
    finalize_kernel<<<1, D>>>(0, g1, be1, invN);
    // layer 2: h2 = relu(bn(h1)) @ W2 + b2 (norm fused into A loader)
    gemm_tc<<<gblocks, 256, SMEM_TOTAL>>>(buf1, 1, b2, buf0, N, 1, 0);
    finalize_kernel<<<1, D>>>(1, g2, be2, invN);
    // final: d_out = relu(bn(h2))
    norm_kernel<<<(total4 + TB - 1) / TB, TB>>>(buf0, 1, (float*)d_out, total4);
}